// round 13
// baseline (speedup 1.0000x reference)
#include <cuda_runtime.h>
#include <cuda_pipeline.h>
#include <cstdint>

// ---------------- problem shape ----------------
#define BB 16
#define NN 2048
#define DD 64
#define BMQ 128             // q rows per CTA (8 warps x 16 rows)
#define BJ 64               // KV rows per tile
#define NT 256              // threads per CTA
#define NTILES (NN / BJ)    // 32

// ---------------- preprocessed tensors (tf32-rounded; Q scaled & Q/K permuted) ----
#define T4 (BB * NN * (DD / 4))     // 524288 float4 per tensor
__device__ float4 g_qpre[T4];
__device__ float4 g_kpre[T4];
__device__ float4 g_vpre[T4];

// ---------------- smem layout (float offsets), pads = 72 ----------------
#define PAD 72
#define SQ 0
#define QF (128 * PAD)              // 9216
#define KTF (BJ * PAD)              // 4608
#define SKB(buf) (QF + (buf) * KTF)
#define SVB(buf) (QF + 2 * KTF + (buf) * KTF)
#define SM_FLOATS (QF + 4 * KTF)    // 27648
#define SMEM_BYTES (SM_FLOATS * 4)  // 110,592 B -> 2 CTAs/SM

// fp32 -> tf32 bits (round-to-nearest, unbiased)
__device__ __forceinline__ uint32_t f2tf(float x) {
    uint32_t u;
    asm("cvt.rna.tf32.f32 %0, %1;" : "=r"(u) : "f"(x));
    return u;
}
__device__ __forceinline__ float f2tf_f(float x) { return __uint_as_float(f2tf(x)); }

// column pair-permutation: within each 8-group, (c, c+4) land at (2*(c&3), 2*(c&3)+1)
__device__ __forceinline__ int permc(int c) {
    return (c & ~7) | ((c & 3) << 1) | ((c >> 2) & 1);
}

// mma.sync m16n8k8 tf32: D = A*B + D (A row-major, B col-major)
__device__ __forceinline__ void mma8(float* c, const uint32_t* a, uint32_t b0, uint32_t b1) {
    asm volatile(
        "mma.sync.aligned.m16n8k8.row.col.f32.tf32.tf32.f32 "
        "{%0,%1,%2,%3}, {%4,%5,%6,%7}, {%8,%9}, {%0,%1,%2,%3};"
        : "+f"(c[0]), "+f"(c[1]), "+f"(c[2]), "+f"(c[3])
        : "r"(a[0]), "r"(a[1]), "r"(a[2]), "r"(a[3]), "r"(b0), "r"(b1));
}

// ---------------- preprocessing: tf32-round, scale Q, permute Q/K columns ----------------
__global__ __launch_bounds__(256)
void prep_kernel(const float* __restrict__ q, const float* __restrict__ k,
                 const float* __restrict__ v)
{
    int id = blockIdx.x * 256 + threadIdx.x;          // 3 * T4 total
    int tens = id >> 19;                              // T4 = 2^19
    int rem = id & (T4 - 1);
    int rowg = rem >> 4;                              // global row (b*NN + n)
    int c4 = rem & 15;
    if (tens == 0) {
        const float4* s = reinterpret_cast<const float4*>(q);
        float4 x = s[rem];
        float* dst = reinterpret_cast<float*>(g_qpre) + (size_t)rowg * DD;
        float xs[4] = {x.x * 0.125f, x.y * 0.125f, x.z * 0.125f, x.w * 0.125f};
        #pragma unroll
        for (int e = 0; e < 4; ++e) dst[permc(4 * c4 + e)] = f2tf_f(xs[e]);
    } else if (tens == 1) {
        const float4* s = reinterpret_cast<const float4*>(k);
        float4 x = s[rem];
        float* dst = reinterpret_cast<float*>(g_kpre) + (size_t)rowg * DD;
        float xs[4] = {x.x, x.y, x.z, x.w};
        #pragma unroll
        for (int e = 0; e < 4; ++e) dst[permc(4 * c4 + e)] = f2tf_f(xs[e]);
    } else {
        const float4* s = reinterpret_cast<const float4*>(v);
        float4 x = s[rem];
        float4 h;
        h.x = f2tf_f(x.x); h.y = f2tf_f(x.y);
        h.z = f2tf_f(x.z); h.w = f2tf_f(x.w);
        g_vpre[rem] = h;
    }
}

// ---------------- main attention kernel ----------------
__global__ __launch_bounds__(NT, 2)
void attn_mma_kernel(const float* __restrict__ edge, const int* __restrict__ mask,
                     float* __restrict__ out)
{
    extern __shared__ float sm[];
    float4* sm4 = reinterpret_cast<float4*>(sm);
    const int b  = blockIdx.y;
    const int q0 = blockIdx.x * BMQ;
    const int t  = threadIdx.x;
    const int w  = t >> 5;        // warp 0..7, rows 16w..16w+15
    const int l  = t & 31;
    const int g  = l >> 2;
    const int qd = l & 3;

    // ---- prologue: async-copy Q tile (b>=2) and KV tile 0 into buffer 0 ----
    if (b >= 2) {
        #pragma unroll
        for (int i = 0; i < 8; ++i) {
            int qc = t + i * NT;             // 2048 chunks
            int row = qc >> 4, cc = qc & 15;
            __pipeline_memcpy_async(&sm4[(SQ + row * PAD) / 4 + cc],
                                    &g_qpre[((size_t)b * NN + q0 + row) * 16 + cc], 16);
        }
        #pragma unroll
        for (int i = 0; i < 4; ++i) {
            int c = t + i * NT;              // 1024 K chunks
            int jl = c >> 4, cc = c & 15;
            __pipeline_memcpy_async(&sm4[SKB(0) / 4 + jl * (PAD / 4) + cc],
                                    &g_kpre[((size_t)b * NN + jl) * 16 + cc], 16);
        }
    }
    #pragma unroll
    for (int i = 0; i < 4; ++i) {
        int c = t + i * NT;                  // 1024 V chunks
        int jl = c >> 4, cc = c & 15;
        __pipeline_memcpy_async(&sm4[SVB(0) / 4 + jl * (PAD / 4) + cc],
                                &g_vpre[((size_t)b * NN + jl) * 16 + cc], 16);
    }
    __pipeline_commit();

    float sacc[8][4];              // S then P fragments (8 n-tiles of BJ=64)
    float oacc[8][4];              // O fragments
    float lsum[2] = {0.f, 0.f};
    #pragma unroll
    for (int n = 0; n < 8; ++n)
        #pragma unroll
        for (int e = 0; e < 4; ++e) oacc[n][e] = 0.f;

    const int row0 = q0 + 16 * w + g;
    const int2*   mrow0 = reinterpret_cast<const int2*>(mask + ((size_t)b * NN + row0) * NN);
    const int2*   mrow1 = reinterpret_cast<const int2*>(mask + ((size_t)b * NN + row0 + 8) * NN);
    const float2* erow0 = reinterpret_cast<const float2*>(edge + (size_t)row0 * NN);
    const float2* erow1 = reinterpret_cast<const float2*>(edge + (size_t)(row0 + 8) * NN);

    for (int kt = 0; kt < NTILES; ++kt) {
        const int j0 = kt * BJ;
        const int buf = kt & 1;

        __pipeline_wait_prior(0);    // this thread's copies for tile kt done
        __syncthreads();             // all threads' copies visible; prev-tile reads done

        // ---- issue next tile's async copies (overlap with this tile's compute) ----
        if (kt + 1 < NTILES) {
            const int nb = (kt + 1) & 1;
            const int jn0 = j0 + BJ;
            if (b >= 2) {
                #pragma unroll
                for (int i = 0; i < 4; ++i) {
                    int c = t + i * NT;
                    int jl = c >> 4, cc = c & 15;
                    __pipeline_memcpy_async(&sm4[SKB(nb) / 4 + jl * (PAD / 4) + cc],
                                            &g_kpre[((size_t)b * NN + jn0 + jl) * 16 + cc], 16);
                }
            }
            #pragma unroll
            for (int i = 0; i < 4; ++i) {
                int c = t + i * NT;
                int jl = c >> 4, cc = c & 15;
                __pipeline_memcpy_async(&sm4[SVB(nb) / 4 + jl * (PAD / 4) + cc],
                                        &g_vpre[((size_t)b * NN + jn0 + jl) * 16 + cc], 16);
            }
        }
        __pipeline_commit();         // always commit (empty group at last iter)

        // ---- prefetch this tile's mask / edge ----
        int2   m0[8], m1[8];
        float2 e0[8], e1[8];
        if (b < 2) {
            #pragma unroll
            for (int nt = 0; nt < 8; ++nt) {
                int c2 = (j0 + 8 * nt + 2 * qd) >> 1;
                e0[nt] = erow0[c2];
                e1[nt] = erow1[c2];
            }
        } else {
            #pragma unroll
            for (int nt = 0; nt < 8; ++nt) {
                int c2 = (j0 + 8 * nt + 2 * qd) >> 1;
                m0[nt] = __ldcs(&mrow0[c2]);
                m1[nt] = __ldcs(&mrow1[c2]);
            }
        }

        // ---- QK^T: S = Q*K (single tf32 term, b>=2) ----
        if (b >= 2) {
            #pragma unroll
            for (int nt = 0; nt < 8; ++nt)
                #pragma unroll
                for (int e = 0; e < 4; ++e) sacc[nt][e] = 0.f;

            #pragma unroll
            for (int kk = 0; kk < 8; ++kk) {
                uint32_t a[4];
                int r0 = 16 * w + g;
                float2 x0 = *reinterpret_cast<const float2*>(&sm[SQ + r0 * PAD + 8 * kk + 2 * qd]);
                float2 x1 = *reinterpret_cast<const float2*>(&sm[SQ + (r0 + 8) * PAD + 8 * kk + 2 * qd]);
                a[0] = __float_as_uint(x0.x); a[1] = __float_as_uint(x1.x);
                a[2] = __float_as_uint(x0.y); a[3] = __float_as_uint(x1.y);
                #pragma unroll
                for (int nt = 0; nt < 8; ++nt) {
                    int jn = 8 * nt + g;
                    float2 bh = *reinterpret_cast<const float2*>(&sm[SKB(buf) + jn * PAD + 8 * kk + 2 * qd]);
                    mma8(sacc[nt], a, __float_as_uint(bh.x), __float_as_uint(bh.y));
                }
            }
        }

        // ---- softmax numerators: P = exp(S) (masked) or exp(edge) ----
        #pragma unroll
        for (int nt = 0; nt < 8; ++nt) {
            float p0, p1, p2, p3;
            if (b < 2) {
                p0 = __expf(e0[nt].x); p1 = __expf(e0[nt].y);
                p2 = __expf(e1[nt].x); p3 = __expf(e1[nt].y);
            } else {
                p0 = m0[nt].x ? 0.f : __expf(sacc[nt][0]);
                p1 = m0[nt].y ? 0.f : __expf(sacc[nt][1]);
                p2 = m1[nt].x ? 0.f : __expf(sacc[nt][2]);
                p3 = m1[nt].y ? 0.f : __expf(sacc[nt][3]);
            }
            float r0f = f2tf_f(p0), r1f = f2tf_f(p1);
            float r2f = f2tf_f(p2), r3f = f2tf_f(p3);
            lsum[0] += r0f + r1f;
            lsum[1] += r2f + r3f;
            sacc[nt][0] = r0f; sacc[nt][1] = r1f;
            sacc[nt][2] = r2f; sacc[nt][3] = r3f;
        }

        // ---- PV: O += P*V. A-frags via quad shuffles ----
        #pragma unroll
        for (int k2 = 0; k2 < 8; ++k2) {
            uint32_t pa[4];
            int src0 = (l & ~3) | (qd >> 1);
            int src1 = src0 + 2;
            float y00 = __shfl_sync(0xffffffffu, sacc[k2][0], src0);
            float y01 = __shfl_sync(0xffffffffu, sacc[k2][1], src0);
            float y10 = __shfl_sync(0xffffffffu, sacc[k2][2], src0);
            float y11 = __shfl_sync(0xffffffffu, sacc[k2][3], src0);
            float z00 = __shfl_sync(0xffffffffu, sacc[k2][0], src1);
            float z01 = __shfl_sync(0xffffffffu, sacc[k2][1], src1);
            float z10 = __shfl_sync(0xffffffffu, sacc[k2][2], src1);
            float z11 = __shfl_sync(0xffffffffu, sacc[k2][3], src1);
            bool od = (qd & 1);
            pa[0] = __float_as_uint(od ? y01 : y00);
            pa[1] = __float_as_uint(od ? y11 : y10);
            pa[2] = __float_as_uint(od ? z01 : z00);
            pa[3] = __float_as_uint(od ? z11 : z10);
            #pragma unroll
            for (int nd = 0; nd < 8; ++nd) {
                int jrow = 8 * k2 + qd;
                uint32_t bh0 = __float_as_uint(sm[SVB(buf) + jrow * PAD + 8 * nd + g]);
                uint32_t bh1 = __float_as_uint(sm[SVB(buf) + (jrow + 4) * PAD + 8 * nd + g]);
                mma8(oacc[nd], pa, bh0, bh1);
            }
        }
        // next iteration's wait+sync protects buffers
    }

    // ---- epilogue: reduce row sums across quad, scale, store ----
    float s0 = lsum[0];
    s0 += __shfl_xor_sync(0xffffffffu, s0, 1);
    s0 += __shfl_xor_sync(0xffffffffu, s0, 2);
    float s1 = lsum[1];
    s1 += __shfl_xor_sync(0xffffffffu, s1, 1);
    s1 += __shfl_xor_sync(0xffffffffu, s1, 2);
    float inv0 = 1.0f / s0, inv1 = 1.0f / s1;
    #pragma unroll
    for (int nd = 0; nd < 8; ++nd) {
        int col = 8 * nd + 2 * qd;
        float2 r0v = make_float2(oacc[nd][0] * inv0, oacc[nd][1] * inv0);
        float2 r1v = make_float2(oacc[nd][2] * inv1, oacc[nd][3] * inv1);
        *reinterpret_cast<float2*>(out + ((size_t)b * NN + row0) * DD + col) = r0v;
        *reinterpret_cast<float2*>(out + ((size_t)b * NN + row0 + 8) * DD + col) = r1v;
    }
}

extern "C" void kernel_launch(void* const* d_in, const int* in_sizes, int n_in,
                              void* d_out, int out_size)
{
    // Input identification (verified Rounds 1-3): q/k/v (2,097,152 elems each)
    // in insertion order q,k,v; edge = N*N; mask = B*N*N delivered as int32.
    const float* q = nullptr; const float* k = nullptr; const float* v = nullptr;
    const float* edge = nullptr; const int* mask = nullptr;

    const int QKV_ELEMS = BB * NN * DD;
    const int EDGE_ELEMS = NN * NN;
    int qkv_seen = 0;
    for (int i = 0; i < n_in; ++i) {
        if (in_sizes[i] == EDGE_ELEMS) edge = (const float*)d_in[i];
        else if (in_sizes[i] == QKV_ELEMS) {
            if (qkv_seen == 0) q = (const float*)d_in[i];
            else if (qkv_seen == 1) k = (const float*)d_in[i];
            else v = (const float*)d_in[i];
            ++qkv_seen;
        } else mask = (const int*)d_in[i];
    }

    // 1) preprocess: tf32-round Q/K/V, scale Q by 1/8, permute Q/K columns
    prep_kernel<<<(3 * T4) / 256, 256>>>(q, k, v);

    // 2) main flash-attention kernel (cp.async pipelined, BJ=64)
    cudaFuncSetAttribute(attn_mma_kernel, cudaFuncAttributeMaxDynamicSharedMemorySize, SMEM_BYTES);
    dim3 grid(NN / BMQ, BB);   // (16, 16) = 256 CTAs
    attn_mma_kernel<<<grid, NT, SMEM_BYTES>>>(edge, mask, (float*)d_out);
}

// round 14
// speedup vs baseline: 1.2035x; 1.2035x over previous
#include <cuda_runtime.h>
#include <cuda_pipeline.h>
#include <cuda_fp16.h>
#include <cstdint>

// ---------------- problem shape ----------------
#define BB 16
#define NN 2048
#define DD 64
#define BMQ 128             // q rows per CTA (8 warps x 16 rows)
#define BJ 64               // KV rows per tile
#define NT 256              // threads per CTA
#define NTILES (NN / BJ)    // 32

// ---------------- preprocessed tensors ----------------
#define T4 (BB * NN * (DD / 4))     // 524288 float4 per tensor
__device__ float4 g_qpre[T4];       // tf32, scaled 1/8, permc-permuted cols
__device__ float4 g_kpre[T4];       // tf32, permc-permuted cols
__device__ __half g_vt[BB * DD * NN];  // fp16, TRANSPOSED [b][d][j], j pair-permuted per 16-group

// ---------------- smem layout (float offsets) ----------------
#define PAD 72              // floats (Q/K rows); Vt rows = 72 halves = 36 floats
#define SQ 0
#define QF (128 * PAD)                       // 9216
#define KTF (BJ * PAD)                       // 4608
#define SKB(buf) (QF + (buf) * KTF)          // 9216 / 13824
#define VTF (DD * 36)                        // 2304 floats per Vt buffer
#define SVTB(buf) (QF + 2 * KTF + (buf) * VTF)   // 18432 / 20736
#define SM_FLOATS (QF + 2 * KTF + 2 * VTF)   // 23040
#define SMEM_BYTES (SM_FLOATS * 4)           // 92,160 B -> 2 CTAs/SM

// fp32 -> tf32 bits (round-to-nearest, unbiased)
__device__ __forceinline__ uint32_t f2tf(float x) {
    uint32_t u;
    asm("cvt.rna.tf32.f32 %0, %1;" : "=r"(u) : "f"(x));
    return u;
}
__device__ __forceinline__ float f2tf_f(float x) { return __uint_as_float(f2tf(x)); }

// column pair-permutation: within each 8-group, (c, c+4) land at (2*(c&3), 2*(c&3)+1)
__device__ __forceinline__ int permc(int c) {
    return (c & ~7) | ((c & 3) << 1) | ((c >> 2) & 1);
}

// mma m16n8k8 tf32 (QK): D = A*B + D
__device__ __forceinline__ void mma8(float* c, const uint32_t* a, uint32_t b0, uint32_t b1) {
    asm volatile(
        "mma.sync.aligned.m16n8k8.row.col.f32.tf32.tf32.f32 "
        "{%0,%1,%2,%3}, {%4,%5,%6,%7}, {%8,%9}, {%0,%1,%2,%3};"
        : "+f"(c[0]), "+f"(c[1]), "+f"(c[2]), "+f"(c[3])
        : "r"(a[0]), "r"(a[1]), "r"(a[2]), "r"(a[3]), "r"(b0), "r"(b1));
}
// mma m16n8k16 fp16 (PV): D = A*B + D, fp32 accum
__device__ __forceinline__ void mma16(float* c, const uint32_t* a, uint32_t b0, uint32_t b1) {
    asm volatile(
        "mma.sync.aligned.m16n8k16.row.col.f32.f16.f16.f32 "
        "{%0,%1,%2,%3}, {%4,%5,%6,%7}, {%8,%9}, {%0,%1,%2,%3};"
        : "+f"(c[0]), "+f"(c[1]), "+f"(c[2]), "+f"(c[3])
        : "r"(a[0]), "r"(a[1]), "r"(a[2]), "r"(a[3]), "r"(b0), "r"(b1));
}

__device__ __forceinline__ uint32_t packh2(float lo, float hi) {
    __half2 h = __floats2half2_rn(lo, hi);
    return *reinterpret_cast<uint32_t*>(&h);
}

// ---------------- prep: Q/K tf32 + permute ----------------
__global__ __launch_bounds__(256)
void prep_qk(const float* __restrict__ q, const float* __restrict__ k)
{
    int id = blockIdx.x * 256 + threadIdx.x;          // 2 * T4 total
    int tens = id >> 19;                              // T4 = 2^19
    int rem = id & (T4 - 1);
    int rowg = rem >> 4;
    int c4 = rem & 15;
    if (tens == 0) {
        float4 x = reinterpret_cast<const float4*>(q)[rem];
        float* dst = reinterpret_cast<float*>(g_qpre) + (size_t)rowg * DD;
        float xs[4] = {x.x * 0.125f, x.y * 0.125f, x.z * 0.125f, x.w * 0.125f};
        #pragma unroll
        for (int e = 0; e < 4; ++e) dst[permc(4 * c4 + e)] = f2tf_f(xs[e]);
    } else {
        float4 x = reinterpret_cast<const float4*>(k)[rem];
        float* dst = reinterpret_cast<float*>(g_kpre) + (size_t)rowg * DD;
        float xs[4] = {x.x, x.y, x.z, x.w};
        #pragma unroll
        for (int e = 0; e < 4; ++e) dst[permc(4 * c4 + e)] = f2tf_f(xs[e]);
    }
}

// ---------------- prep: V transpose to [b][d][j] fp16, j pair-permuted ----------------
// Output j-order within each 16-group: [0,1,8,9, 2,3,10,11, 4,5,12,13, 6,7,14,15]
// so the PV B-fragment {(2qd,2qd+1),(2qd+8,2qd+9)} is one contiguous 8-byte load.
__global__ __launch_bounds__(256)
void prep_vt(const float* __restrict__ v)
{
    __shared__ float smt[64][65];
    int b  = blockIdx.y;
    int j0 = blockIdx.x * 64;
    int t  = threadIdx.x;

    // load 64j x 64d tile (coalesced float4 reads)
    #pragma unroll
    for (int i = 0; i < 4; ++i) {
        int idx = t + i * 256;               // 1024 float4
        int jj = idx >> 4, c4 = idx & 15;
        float4 x = reinterpret_cast<const float4*>(v)[((size_t)b * NN + j0 + jj) * 16 + c4];
        smt[jj][4 * c4]     = x.x;
        smt[jj][4 * c4 + 1] = x.y;
        smt[jj][4 * c4 + 2] = x.z;
        smt[jj][4 * c4 + 3] = x.w;
    }
    __syncthreads();

    // write transposed+permuted (coalesced half2 stores along j)
    int hu = t & 31;                          // output half2-unit within the 64-j row
    int grp = hu >> 3, pos = hu & 7;
    int m8 = (pos >> 1) + ((pos & 1) << 2);   // inverse of pos = 2*(m&3) + (m>>2)
    int m = grp * 8 + m8;                     // source j-pair index
    #pragma unroll
    for (int p = 0; p < 8; ++p) {
        int d = (t >> 5) + 8 * p;
        __half2 h = __floats2half2_rn(smt[2 * m][d], smt[2 * m + 1][d]);
        *reinterpret_cast<__half2*>(g_vt + (size_t)(b * DD + d) * NN + j0 + 2 * hu) = h;
    }
}

// ---------------- main attention kernel ----------------
__global__ __launch_bounds__(NT, 2)
void attn_mma_kernel(const float* __restrict__ edge, const int* __restrict__ mask,
                     float* __restrict__ out)
{
    extern __shared__ float sm[];
    float4* sm4 = reinterpret_cast<float4*>(sm);
    const int b  = blockIdx.y;
    const int q0 = blockIdx.x * BMQ;
    const int t  = threadIdx.x;
    const int w  = t >> 5;
    const int l  = t & 31;
    const int g  = l >> 2;
    const int qd = l & 3;

    // ---- prologue: async-copy Q tile (b>=2), K tile 0 (b>=2), Vt tile 0 ----
    if (b >= 2) {
        #pragma unroll
        for (int i = 0; i < 8; ++i) {
            int qc = t + i * NT;
            int row = qc >> 4, cc = qc & 15;
            __pipeline_memcpy_async(&sm4[(SQ + row * PAD) / 4 + cc],
                                    &g_qpre[((size_t)b * NN + q0 + row) * 16 + cc], 16);
        }
        #pragma unroll
        for (int i = 0; i < 4; ++i) {
            int c = t + i * NT;
            int jl = c >> 4, cc = c & 15;
            __pipeline_memcpy_async(&sm4[SKB(0) / 4 + jl * (PAD / 4) + cc],
                                    &g_kpre[((size_t)b * NN + jl) * 16 + cc], 16);
        }
    }
    #pragma unroll
    for (int i = 0; i < 2; ++i) {
        int c = t + i * NT;                  // 512 chunks: row d = c>>3, 8 x 16B per row
        int d = c >> 3, cc = c & 7;
        __pipeline_memcpy_async(&sm4[SVTB(0) / 4 + d * 9 + cc],
                                g_vt + ((size_t)(b * DD + d) * NN) + cc * 8, 16);
    }
    __pipeline_commit();

    float sacc[8][4];              // S then P (fp32, unrounded)
    float oacc[8][4];
    float lsum[2] = {0.f, 0.f};
    #pragma unroll
    for (int n = 0; n < 8; ++n)
        #pragma unroll
        for (int e = 0; e < 4; ++e) oacc[n][e] = 0.f;

    const int row0 = q0 + 16 * w + g;
    const int2*   mrow0 = reinterpret_cast<const int2*>(mask + ((size_t)b * NN + row0) * NN);
    const int2*   mrow1 = reinterpret_cast<const int2*>(mask + ((size_t)b * NN + row0 + 8) * NN);
    const float2* erow0 = reinterpret_cast<const float2*>(edge + (size_t)row0 * NN);
    const float2* erow1 = reinterpret_cast<const float2*>(edge + (size_t)(row0 + 8) * NN);

    for (int kt = 0; kt < NTILES; ++kt) {
        const int j0 = kt * BJ;
        const int buf = kt & 1;

        __pipeline_wait_prior(0);
        __syncthreads();

        // ---- issue next tile's async copies ----
        if (kt + 1 < NTILES) {
            const int nb = (kt + 1) & 1;
            const int jn0 = j0 + BJ;
            if (b >= 2) {
                #pragma unroll
                for (int i = 0; i < 4; ++i) {
                    int c = t + i * NT;
                    int jl = c >> 4, cc = c & 15;
                    __pipeline_memcpy_async(&sm4[SKB(nb) / 4 + jl * (PAD / 4) + cc],
                                            &g_kpre[((size_t)b * NN + jn0 + jl) * 16 + cc], 16);
                }
            }
            #pragma unroll
            for (int i = 0; i < 2; ++i) {
                int c = t + i * NT;
                int d = c >> 3, cc = c & 7;
                __pipeline_memcpy_async(&sm4[SVTB(nb) / 4 + d * 9 + cc],
                                        g_vt + ((size_t)(b * DD + d) * NN + jn0) + cc * 8, 16);
            }
        }
        __pipeline_commit();

        // ---- prefetch this tile's mask / edge ----
        int2   m0[8], m1[8];
        float2 e0[8], e1[8];
        if (b < 2) {
            #pragma unroll
            for (int nt = 0; nt < 8; ++nt) {
                int c2 = (j0 + 8 * nt + 2 * qd) >> 1;
                e0[nt] = erow0[c2];
                e1[nt] = erow1[c2];
            }
        } else {
            #pragma unroll
            for (int nt = 0; nt < 8; ++nt) {
                int c2 = (j0 + 8 * nt + 2 * qd) >> 1;
                m0[nt] = __ldcs(&mrow0[c2]);
                m1[nt] = __ldcs(&mrow1[c2]);
            }
        }

        // ---- QK^T: S = Q*K (tf32, b>=2) ----
        if (b >= 2) {
            #pragma unroll
            for (int nt = 0; nt < 8; ++nt)
                #pragma unroll
                for (int e = 0; e < 4; ++e) sacc[nt][e] = 0.f;

            #pragma unroll
            for (int kk = 0; kk < 8; ++kk) {
                uint32_t a[4];
                int r0 = 16 * w + g;
                float2 x0 = *reinterpret_cast<const float2*>(&sm[SQ + r0 * PAD + 8 * kk + 2 * qd]);
                float2 x1 = *reinterpret_cast<const float2*>(&sm[SQ + (r0 + 8) * PAD + 8 * kk + 2 * qd]);
                a[0] = __float_as_uint(x0.x); a[1] = __float_as_uint(x1.x);
                a[2] = __float_as_uint(x0.y); a[3] = __float_as_uint(x1.y);
                #pragma unroll
                for (int nt = 0; nt < 8; ++nt) {
                    int jn = 8 * nt + g;
                    float2 bh = *reinterpret_cast<const float2*>(&sm[SKB(buf) + jn * PAD + 8 * kk + 2 * qd]);
                    mma8(sacc[nt], a, __float_as_uint(bh.x), __float_as_uint(bh.y));
                }
            }
        }

        // ---- softmax numerators: P = exp(S) (masked) or exp(edge); fp32, unrounded ----
        #pragma unroll
        for (int nt = 0; nt < 8; ++nt) {
            float p0, p1, p2, p3;
            if (b < 2) {
                p0 = __expf(e0[nt].x); p1 = __expf(e0[nt].y);
                p2 = __expf(e1[nt].x); p3 = __expf(e1[nt].y);
            } else {
                p0 = m0[nt].x ? 0.f : __expf(sacc[nt][0]);
                p1 = m0[nt].y ? 0.f : __expf(sacc[nt][1]);
                p2 = m1[nt].x ? 0.f : __expf(sacc[nt][2]);
                p3 = m1[nt].y ? 0.f : __expf(sacc[nt][3]);
            }
            lsum[0] += p0 + p1;
            lsum[1] += p2 + p3;
            sacc[nt][0] = p0; sacc[nt][1] = p1;
            sacc[nt][2] = p2; sacc[nt][3] = p3;
        }

        // ---- PV: O += P*V (fp16 m16n8k16). A = packed C-frags (NO shuffles) ----
        const __half* vt = reinterpret_cast<const __half*>(sm + SVTB(buf));
        #pragma unroll
        for (int kc = 0; kc < 4; ++kc) {
            uint32_t pa[4];
            pa[0] = packh2(sacc[2 * kc][0],     sacc[2 * kc][1]);
            pa[1] = packh2(sacc[2 * kc][2],     sacc[2 * kc][3]);
            pa[2] = packh2(sacc[2 * kc + 1][0], sacc[2 * kc + 1][1]);
            pa[3] = packh2(sacc[2 * kc + 1][2], sacc[2 * kc + 1][3]);
            #pragma unroll
            for (int nd = 0; nd < 8; ++nd) {
                int vrow = 8 * nd + g;   // Vt row = output dim d
                uint2 bb = *reinterpret_cast<const uint2*>(vt + vrow * 72 + kc * 16 + 4 * qd);
                mma16(oacc[nd], pa, bb.x, bb.y);
            }
        }
    }

    // ---- epilogue ----
    float s0 = lsum[0];
    s0 += __shfl_xor_sync(0xffffffffu, s0, 1);
    s0 += __shfl_xor_sync(0xffffffffu, s0, 2);
    float s1 = lsum[1];
    s1 += __shfl_xor_sync(0xffffffffu, s1, 1);
    s1 += __shfl_xor_sync(0xffffffffu, s1, 2);
    float inv0 = 1.0f / s0, inv1 = 1.0f / s1;
    #pragma unroll
    for (int nd = 0; nd < 8; ++nd) {
        int col = 8 * nd + 2 * qd;
        float2 r0v = make_float2(oacc[nd][0] * inv0, oacc[nd][1] * inv0);
        float2 r1v = make_float2(oacc[nd][2] * inv1, oacc[nd][3] * inv1);
        *reinterpret_cast<float2*>(out + ((size_t)b * NN + row0) * DD + col) = r0v;
        *reinterpret_cast<float2*>(out + ((size_t)b * NN + row0 + 8) * DD + col) = r1v;
    }
}

extern "C" void kernel_launch(void* const* d_in, const int* in_sizes, int n_in,
                              void* d_out, int out_size)
{
    // Input identification (verified Rounds 1-3): q/k/v in insertion order;
    // edge = N*N; mask = B*N*N delivered as int32.
    const float* q = nullptr; const float* k = nullptr; const float* v = nullptr;
    const float* edge = nullptr; const int* mask = nullptr;

    const int QKV_ELEMS = BB * NN * DD;
    const int EDGE_ELEMS = NN * NN;
    int qkv_seen = 0;
    for (int i = 0; i < n_in; ++i) {
        if (in_sizes[i] == EDGE_ELEMS) edge = (const float*)d_in[i];
        else if (in_sizes[i] == QKV_ELEMS) {
            if (qkv_seen == 0) q = (const float*)d_in[i];
            else if (qkv_seen == 1) k = (const float*)d_in[i];
            else v = (const float*)d_in[i];
            ++qkv_seen;
        } else mask = (const int*)d_in[i];
    }

    prep_qk<<<(2 * T4) / 256, 256>>>(q, k);
    prep_vt<<<dim3(NN / 64, BB), 256>>>(v);

    cudaFuncSetAttribute(attn_mma_kernel, cudaFuncAttributeMaxDynamicSharedMemorySize, SMEM_BYTES);
    dim3 grid(NN / BMQ, BB);   // (16, 16) = 256 CTAs
    attn_mma_kernel<<<grid, NT, SMEM_BYTES>>>(edge, mask, (float*)d_out);
}

// round 16
// speedup vs baseline: 1.5201x; 1.2631x over previous
#include <cuda_runtime.h>
#include <cuda_pipeline.h>
#include <cuda_fp16.h>
#include <cstdint>

// ---------------- problem shape ----------------
#define BB 16
#define NN 2048
#define DD 64
#define BMQ 128             // q rows per CTA (8 warps x 16 rows)
#define BJ 64               // KV rows per tile
#define NT 256              // threads per CTA
#define NTILES (NN / BJ)    // 32

// ---------------- preprocessed tensors (all fp16, rn-rounded) ----------------
__device__ __half g_qh[BB * NN * DD];   // scaled 1/8, k-dim pair-permuted (permh)
__device__ __half g_kh[BB * NN * DD];   // k-dim pair-permuted (permh)
__device__ __half g_vt[BB * DD * NN];   // TRANSPOSED [b][d][j], j pair-permuted per 16-group

// ---------------- smem layout (float offsets). Row = 80 halves = 40 floats ----------------
#define QW 40
#define SQ 0
#define QF (128 * QW)                        // 5120
#define KTF (BJ * QW)                        // 2560
#define SKB(buf) (QF + (buf) * KTF)
#define SVTB(buf) (QF + 2 * KTF + (buf) * KTF)
#define SM_FLOATS (QF + 4 * KTF)             // 15360
#define SMEM_BYTES (SM_FLOATS * 4)           // 61,440 B -> 2 CTAs/SM

// pair-permutation on a 16-element k-group: pair m -> slot 2*(m&3) + (m>>2),
// so fragment pairs (qd, qd+4) land adjacent (one uint2 load).
__device__ __forceinline__ int permh(int c) {
    int m = (c >> 1) & 7;
    int slot = ((m & 3) << 1) | (m >> 2);
    return (c & ~15) | (slot << 1) | (c & 1);
}

// mma m16n8k16 fp16, fp32 accum: D = A*B + D (A row-major, B col-major)
__device__ __forceinline__ void mma16(float* c, const uint32_t* a, uint32_t b0, uint32_t b1) {
    asm volatile(
        "mma.sync.aligned.m16n8k16.row.col.f32.f16.f16.f32 "
        "{%0,%1,%2,%3}, {%4,%5,%6,%7}, {%8,%9}, {%0,%1,%2,%3};"
        : "+f"(c[0]), "+f"(c[1]), "+f"(c[2]), "+f"(c[3])
        : "r"(a[0]), "r"(a[1]), "r"(a[2]), "r"(a[3]), "r"(b0), "r"(b1));
}

__device__ __forceinline__ uint32_t packh2(float lo, float hi) {
    __half2 h = __floats2half2_rn(lo, hi);
    return *reinterpret_cast<uint32_t*>(&h);
}

// ---------------- prep: Q/K -> fp16, Q scaled, k-dim permh-permuted ----------------
__global__ __launch_bounds__(256)
void prep_qk(const float* __restrict__ q, const float* __restrict__ k)
{
    const int T4 = BB * NN * (DD / 4);                // 2^19 float4 per tensor
    int id = blockIdx.x * 256 + threadIdx.x;          // 2 * T4 total
    int tens = id >> 19;
    int rem = id & (T4 - 1);
    int rowg = rem >> 4;
    int c4 = rem & 15;
    if (tens == 0) {
        float4 x = reinterpret_cast<const float4*>(q)[rem];
        __half* dst = g_qh + (size_t)rowg * DD;
        float xs[4] = {x.x * 0.125f, x.y * 0.125f, x.z * 0.125f, x.w * 0.125f};
        #pragma unroll
        for (int e = 0; e < 4; ++e) dst[permh(4 * c4 + e)] = __float2half_rn(xs[e]);
    } else {
        float4 x = reinterpret_cast<const float4*>(k)[rem];
        __half* dst = g_kh + (size_t)rowg * DD;
        float xs[4] = {x.x, x.y, x.z, x.w};
        #pragma unroll
        for (int e = 0; e < 4; ++e) dst[permh(4 * c4 + e)] = __float2half_rn(xs[e]);
    }
}

// ---------------- prep: V transpose to [b][d][j] fp16, j pair-permuted ----------------
__global__ __launch_bounds__(256)
void prep_vt(const float* __restrict__ v)
{
    __shared__ float smt[64][65];
    int b  = blockIdx.y;
    int j0 = blockIdx.x * 64;
    int t  = threadIdx.x;

    #pragma unroll
    for (int i = 0; i < 4; ++i) {
        int idx = t + i * 256;
        int jj = idx >> 4, c4 = idx & 15;
        float4 x = reinterpret_cast<const float4*>(v)[((size_t)b * NN + j0 + jj) * 16 + c4];
        smt[jj][4 * c4]     = x.x;
        smt[jj][4 * c4 + 1] = x.y;
        smt[jj][4 * c4 + 2] = x.z;
        smt[jj][4 * c4 + 3] = x.w;
    }
    __syncthreads();

    int hu = t & 31;
    int grp = hu >> 3, pos = hu & 7;
    int m8 = (pos >> 1) + ((pos & 1) << 2);   // inverse of slot = 2*(m&3) + (m>>2)
    int m = grp * 8 + m8;
    #pragma unroll
    for (int p = 0; p < 8; ++p) {
        int d = (t >> 5) + 8 * p;
        __half2 h = __floats2half2_rn(smt[2 * m][d], smt[2 * m + 1][d]);
        *reinterpret_cast<__half2*>(g_vt + (size_t)(b * DD + d) * NN + j0 + 2 * hu) = h;
    }
}

// ---------------- main attention kernel ----------------
__global__ __launch_bounds__(NT, 2)
void attn_mma_kernel(const float* __restrict__ edge, const int* __restrict__ mask,
                     float* __restrict__ out)
{
    extern __shared__ float sm[];
    float4* sm4 = reinterpret_cast<float4*>(sm);
    const __half* shh = reinterpret_cast<const __half*>(sm);
    const int b  = blockIdx.y;
    const int q0 = blockIdx.x * BMQ;
    const int t  = threadIdx.x;
    const int w  = t >> 5;
    const int l  = t & 31;
    const int g  = l >> 2;
    const int qd = l & 3;

    // ---- prologue: async-copy Q tile (b>=2), K tile 0 (b>=2), Vt tile 0 ----
    if (b >= 2) {
        #pragma unroll
        for (int i = 0; i < 4; ++i) {
            int qc = t + i * NT;             // 1024 chunks (128 rows x 8)
            int row = qc >> 3, cc = qc & 7;
            __pipeline_memcpy_async(&sm4[row * (QW / 4) + cc],
                                    g_qh + ((size_t)(b * NN + q0 + row)) * DD + cc * 8, 16);
        }
        #pragma unroll
        for (int i = 0; i < 2; ++i) {
            int c = t + i * NT;              // 512 chunks (64 rows x 8)
            int jl = c >> 3, cc = c & 7;
            __pipeline_memcpy_async(&sm4[SKB(0) / 4 + jl * (QW / 4) + cc],
                                    g_kh + ((size_t)(b * NN + jl)) * DD + cc * 8, 16);
        }
    }
    #pragma unroll
    for (int i = 0; i < 2; ++i) {
        int c = t + i * NT;                  // 512 chunks (64 d-rows x 8)
        int d = c >> 3, cc = c & 7;
        __pipeline_memcpy_async(&sm4[SVTB(0) / 4 + d * (QW / 4) + cc],
                                g_vt + ((size_t)(b * DD + d) * NN) + cc * 8, 16);
    }
    __pipeline_commit();

    float sacc[8][4];              // S then P (fp32)
    float oacc[8][4];
    float lsum[2] = {0.f, 0.f};
    #pragma unroll
    for (int n = 0; n < 8; ++n)
        #pragma unroll
        for (int e = 0; e < 4; ++e) oacc[n][e] = 0.f;

    const int row0 = q0 + 16 * w + g;
    const int2*   mrow0 = reinterpret_cast<const int2*>(mask + ((size_t)b * NN + row0) * NN);
    const int2*   mrow1 = reinterpret_cast<const int2*>(mask + ((size_t)b * NN + row0 + 8) * NN);
    const float2* erow0 = reinterpret_cast<const float2*>(edge + (size_t)row0 * NN);
    const float2* erow1 = reinterpret_cast<const float2*>(edge + (size_t)(row0 + 8) * NN);

    for (int kt = 0; kt < NTILES; ++kt) {
        const int j0 = kt * BJ;
        const int buf = kt & 1;

        __pipeline_wait_prior(0);
        __syncthreads();

        // ---- issue next tile's async copies ----
        if (kt + 1 < NTILES) {
            const int nb = (kt + 1) & 1;
            const int jn0 = j0 + BJ;
            if (b >= 2) {
                #pragma unroll
                for (int i = 0; i < 2; ++i) {
                    int c = t + i * NT;
                    int jl = c >> 3, cc = c & 7;
                    __pipeline_memcpy_async(&sm4[SKB(nb) / 4 + jl * (QW / 4) + cc],
                                            g_kh + ((size_t)(b * NN + jn0 + jl)) * DD + cc * 8, 16);
                }
            }
            #pragma unroll
            for (int i = 0; i < 2; ++i) {
                int c = t + i * NT;
                int d = c >> 3, cc = c & 7;
                __pipeline_memcpy_async(&sm4[SVTB(nb) / 4 + d * (QW / 4) + cc],
                                        g_vt + ((size_t)(b * DD + d) * NN + jn0) + cc * 8, 16);
            }
        }
        __pipeline_commit();

        // ---- prefetch this tile's mask / edge ----
        int2   m0[8], m1[8];
        float2 e0[8], e1[8];
        if (b < 2) {
            #pragma unroll
            for (int nt = 0; nt < 8; ++nt) {
                int c2 = (j0 + 8 * nt + 2 * qd) >> 1;
                e0[nt] = erow0[c2];
                e1[nt] = erow1[c2];
            }
        } else {
            #pragma unroll
            for (int nt = 0; nt < 8; ++nt) {
                int c2 = (j0 + 8 * nt + 2 * qd) >> 1;
                m0[nt] = __ldcs(&mrow0[c2]);
                m1[nt] = __ldcs(&mrow1[c2]);
            }
        }

        // ---- QK^T: S = Q*K (fp16 m16n8k16, fp32 accum; b>=2) ----
        if (b >= 2) {
            #pragma unroll
            for (int nt = 0; nt < 8; ++nt)
                #pragma unroll
                for (int e = 0; e < 4; ++e) sacc[nt][e] = 0.f;

            const __half* kh = shh + SKB(buf) * 2;   // float offset -> half offset
            #pragma unroll
            for (int kc = 0; kc < 4; ++kc) {
                int r0 = 16 * w + g;
                uint2 qa0 = *reinterpret_cast<const uint2*>(shh + r0 * 80 + kc * 16 + 4 * qd);
                uint2 qa1 = *reinterpret_cast<const uint2*>(shh + (r0 + 8) * 80 + kc * 16 + 4 * qd);
                uint32_t a[4] = {qa0.x, qa1.x, qa0.y, qa1.y};
                #pragma unroll
                for (int nt = 0; nt < 8; ++nt) {
                    int jn = 8 * nt + g;
                    uint2 kb2 = *reinterpret_cast<const uint2*>(kh + jn * 80 + kc * 16 + 4 * qd);
                    mma16(sacc[nt], a, kb2.x, kb2.y);
                }
            }
        }

        // ---- softmax numerators: P = exp(S) (masked) or exp(edge) ----
        #pragma unroll
        for (int nt = 0; nt < 8; ++nt) {
            float p0, p1, p2, p3;
            if (b < 2) {
                p0 = __expf(e0[nt].x); p1 = __expf(e0[nt].y);
                p2 = __expf(e1[nt].x); p3 = __expf(e1[nt].y);
            } else {
                p0 = m0[nt].x ? 0.f : __expf(sacc[nt][0]);
                p1 = m0[nt].y ? 0.f : __expf(sacc[nt][1]);
                p2 = m1[nt].x ? 0.f : __expf(sacc[nt][2]);
                p3 = m1[nt].y ? 0.f : __expf(sacc[nt][3]);
            }
            lsum[0] += p0 + p1;
            lsum[1] += p2 + p3;
            sacc[nt][0] = p0; sacc[nt][1] = p1;
            sacc[nt][2] = p2; sacc[nt][3] = p3;
        }

        // ---- PV: O += P*V (fp16 m16n8k16). A = packed C-frags (no shuffles) ----
        const __half* vt = shh + SVTB(buf) * 2;
        #pragma unroll
        for (int kc = 0; kc < 4; ++kc) {
            uint32_t pa[4];
            pa[0] = packh2(sacc[2 * kc][0],     sacc[2 * kc][1]);
            pa[1] = packh2(sacc[2 * kc][2],     sacc[2 * kc][3]);
            pa[2] = packh2(sacc[2 * kc + 1][0], sacc[2 * kc + 1][1]);
            pa[3] = packh2(sacc[2 * kc + 1][2], sacc[2 * kc + 1][3]);
            #pragma unroll
            for (int nd = 0; nd < 8; ++nd) {
                int vrow = 8 * nd + g;   // Vt row = output dim d
                uint2 bb = *reinterpret_cast<const uint2*>(vt + vrow * 80 + kc * 16 + 4 * qd);
                mma16(oacc[nd], pa, bb.x, bb.y);
            }
        }
    }

    // ---- epilogue ----
    float s0 = lsum[0];
    s0 += __shfl_xor_sync(0xffffffffu, s0, 1);
    s0 += __shfl_xor_sync(0xffffffffu, s0, 2);
    float s1 = lsum[1];
    s1 += __shfl_xor_sync(0xffffffffu, s1, 1);
    s1 += __shfl_xor_sync(0xffffffffu, s1, 2);
    float inv0 = 1.0f / s0, inv1 = 1.0f / s1;
    #pragma unroll
    for (int nd = 0; nd < 8; ++nd) {
        int col = 8 * nd + 2 * qd;
        float2 r0v = make_float2(oacc[nd][0] * inv0, oacc[nd][1] * inv0);
        float2 r1v = make_float2(oacc[nd][2] * inv1, oacc[nd][3] * inv1);
        *reinterpret_cast<float2*>(out + ((size_t)b * NN + row0) * DD + col) = r0v;
        *reinterpret_cast<float2*>(out + ((size_t)b * NN + row0 + 8) * DD + col) = r1v;
    }
}

extern "C" void kernel_launch(void* const* d_in, const int* in_sizes, int n_in,
                              void* d_out, int out_size)
{
    // Input identification (verified Rounds 1-3): q/k/v in insertion order;
    // edge = N*N; mask = B*N*N delivered as int32.
    const float* q = nullptr; const float* k = nullptr; const float* v = nullptr;
    const float* edge = nullptr; const int* mask = nullptr;

    const int QKV_ELEMS = BB * NN * DD;
    const int EDGE_ELEMS = NN * NN;
    int qkv_seen = 0;
    for (int i = 0; i < n_in; ++i) {
        if (in_sizes[i] == EDGE_ELEMS) edge = (const float*)d_in[i];
        else if (in_sizes[i] == QKV_ELEMS) {
            if (qkv_seen == 0) q = (const float*)d_in[i];
            else if (qkv_seen == 1) k = (const float*)d_in[i];
            else v = (const float*)d_in[i];
            ++qkv_seen;
        } else mask = (const int*)d_in[i];
    }

    prep_qk<<<(2 * BB * NN * (DD / 4)) / 256, 256>>>(q, k);
    prep_vt<<<dim3(NN / 64, BB), 256>>>(v);

    cudaFuncSetAttribute(attn_mma_kernel, cudaFuncAttributeMaxDynamicSharedMemorySize, SMEM_BYTES);
    dim3 grid(NN / BMQ, BB);   // (16, 16) = 256 CTAs
    attn_mma_kernel<<<grid, NT, SMEM_BYTES>>>(edge, mask, (float*)d_out);
}